// round 2
// baseline (speedup 1.0000x reference)
#include <cuda_runtime.h>

#define BB 128
#define TT 4096
#define KK 64
#define START 62
#define STOP 63
#define NEGV -10000.0f

// backpointer scratch: 128 * 4096 * 64 = 32 MB
__device__ unsigned char g_bp[(size_t)BB * TT * KK];

__device__ __forceinline__ void barF() { asm volatile("bar.sync 1, 128;" ::: "memory"); }
__device__ __forceinline__ void barV() { asm volatile("bar.sync 2, 128;" ::: "memory"); }

__global__ __launch_bounds__(256, 1)
void crf_kernel(const float* __restrict__ feats,
                const int*   __restrict__ tags,
                const float* __restrict__ trans,
                float*       __restrict__ out)
{
    __shared__ __align__(16) float a_buf[2][KK];
    __shared__ __align__(16) float d_buf[2][KK];
    __shared__ float redF[4];
    __shared__ float gred[128];
    __shared__ __align__(16) unsigned char bt[64 * KK];

    const int b   = blockIdx.x;
    const int tid = threadIdx.x;
    const float* bf = feats + (size_t)b * TT * KK;
    const int*   btags = tags + (size_t)b * TT;
    unsigned char* bpb = g_bp + (size_t)b * TT * KK;

    if (tid < 128) {
        // ---------------- FORWARD GROUP (warps 0-3) ----------------
        const int j = tid >> 1;
        const int h = tid & 1;
        float E[32];
#pragma unroll
        for (int i = 0; i < 32; i++) E[i] = __expf(trans[j * KK + h * 32 + i]);

        if (h == 0) a_buf[0][j] = (j == START) ? 1.0f : 0.0f;
        barF();

        float logscale = 0.0f;
        int p = 0;
        float f0 = bf[0 * KK + j];
        float f1 = bf[1 * KK + j];

        for (int t = 0; t < TT; t++) {
            float f2 = (t + 2 < TT) ? bf[(size_t)(t + 2) * KK + j] : 0.0f;

            const float4* av = (const float4*)(&a_buf[p][h * 32]);
            float d0 = 0.f, d1 = 0.f, d2 = 0.f, d3 = 0.f;
#pragma unroll
            for (int k = 0; k < 8; k++) {
                float4 a4 = av[k];
                d0 = fmaf(E[4 * k + 0], a4.x, d0);
                d1 = fmaf(E[4 * k + 1], a4.y, d1);
                d2 = fmaf(E[4 * k + 2], a4.z, d2);
                d3 = fmaf(E[4 * k + 3], a4.w, d3);
            }
            float dot = (d0 + d1) + (d2 + d3);
            dot += __shfl_xor_sync(0xffffffffu, dot, 1);

            float lin = __expf(f0) * dot;

            // warp-wide max of lin (16 distinct states per warp, dup pairs fine)
            float m = lin;
#pragma unroll
            for (int s = 16; s >= 1; s >>= 1)
                m = fmaxf(m, __shfl_xor_sync(0xffffffffu, m, s));
            if ((tid & 31) == 0) redF[tid >> 5] = m;
            barF();
            float M = fmaxf(fmaxf(redF[0], redF[1]), fmaxf(redF[2], redF[3]));
            float rM = 1.0f / M;
            if (h == 0) a_buf[p ^ 1][j] = lin * rM;
            logscale += __logf(M);
            barF();
            p ^= 1;
            f0 = f1; f1 = f2;
        }

        // ---- gold score (parallel over t) ----
        float g = 0.0f;
        for (int t = tid; t < TT; t += 128) {
            int tag  = btags[t];
            int prev = (t == 0) ? START : btags[t - 1];
            g += trans[tag * KK + prev] + bf[(size_t)t * KK + tag];
        }
        gred[tid] = g;
        barF();
        if (tid == 0) {
            float gold = 0.0f;
            for (int i = 0; i < 128; i++) gold += gred[i];
            gold += trans[STOP * KK + btags[TT - 1]];
            float s = 0.0f;
            for (int i = 0; i < KK; i++)
                s += a_buf[p][i] * __expf(trans[STOP * KK + i]);
            float fwd = logscale + __logf(s);
            out[b] = fwd - gold;   // nll
        }
    } else {
        // ---------------- VITERBI GROUP (warps 4-7) ----------------
        const int vt = tid - 128;
        const int j = vt >> 1;
        const int h = vt & 1;
        float Tr[32];
#pragma unroll
        for (int i = 0; i < 32; i++) Tr[i] = trans[j * KK + h * 32 + i];

        if (h == 0) d_buf[0][j] = (j == START) ? 0.0f : NEGV;
        barV();

        int p = 0;
        float f0 = bf[0 * KK + j];
        float f1 = bf[1 * KK + j];

        for (int t = 0; t < TT; t++) {
            float f2 = (t + 2 < TT) ? bf[(size_t)(t + 2) * KK + j] : 0.0f;

            const float4* dv = (const float4*)(&d_buf[p][h * 32]);
            // 4 independent (value,index) chains to cut dependency depth
            float bv0 = -3.0e38f, bv1 = -3.0e38f, bv2 = -3.0e38f, bv3 = -3.0e38f;
            int   bi0 = 0, bi1 = 0, bi2 = 0, bi3 = 0;
#pragma unroll
            for (int k = 0; k < 8; k++) {
                float4 d4 = dv[k];
                float v;
                v = Tr[4 * k + 0] + d4.x; if (v > bv0) { bv0 = v; bi0 = h * 32 + 4 * k + 0; }
                v = Tr[4 * k + 1] + d4.y; if (v > bv1) { bv1 = v; bi1 = h * 32 + 4 * k + 1; }
                v = Tr[4 * k + 2] + d4.z; if (v > bv2) { bv2 = v; bi2 = h * 32 + 4 * k + 2; }
                v = Tr[4 * k + 3] + d4.w; if (v > bv3) { bv3 = v; bi3 = h * 32 + 4 * k + 3; }
            }
            // merge chains, preferring smaller index on exact ties (first-max)
            float bv = bv0; int bi = bi0;
            if (bv1 > bv || (bv1 == bv && bi1 < bi)) { bv = bv1; bi = bi1; }
            if (bv2 > bv || (bv2 == bv && bi2 < bi)) { bv = bv2; bi = bi2; }
            if (bv3 > bv || (bv3 == bv && bi3 < bi)) { bv = bv3; bi = bi3; }

            float ob = __shfl_xor_sync(0xffffffffu, bv, 1);
            int   oi = __shfl_xor_sync(0xffffffffu, bi, 1);
            float lo_v = (h == 0) ? bv : ob;  int lo_i = (h == 0) ? bi : oi;
            float hi_v = (h == 0) ? ob : bv;  int hi_i = (h == 0) ? oi : bi;
            float fbv; int fbi;
            if (hi_v > lo_v) { fbv = hi_v; fbi = hi_i; } else { fbv = lo_v; fbi = lo_i; }

            if (h == 0) {
                d_buf[p ^ 1][j] = fbv + f0;
                bpb[(size_t)t * KK + j] = (unsigned char)fbi;
            }
            barV();
            p ^= 1;
            f0 = f1; f1 = f2;
        }

        // ---- terminal + path score (thread vt==0) ----
        int cur = 0;
        if (vt == 0) {
            float best = -3.0e38f; int blast = 0;
            for (int i = 0; i < KK; i++) {
                float v = d_buf[p][i] + trans[STOP * KK + i];
                if (v > best) { best = v; blast = i; }
            }
            out[BB + b] = best;    // path_score
            cur = blast;
        }
        __threadfence_block();

        // ---- backtrack in 64-step chunks staged through shared ----
        float* pathout = out + 2 * BB + (size_t)b * TT;
        for (int t0 = TT - 64; t0 >= 0; t0 -= 64) {
            const uint4* src = (const uint4*)(bpb + (size_t)t0 * KK);
            uint4* dst = (uint4*)bt;
            dst[vt * 2 + 0] = src[vt * 2 + 0];
            dst[vt * 2 + 1] = src[vt * 2 + 1];
            barV();
            if (vt == 0) {
#pragma unroll 4
                for (int tt = 63; tt >= 0; tt--) {
                    pathout[t0 + tt] = (float)cur;
                    cur = bt[tt * KK + cur];
                }
            }
            barV();
        }
    }
}

extern "C" void kernel_launch(void* const* d_in, const int* in_sizes, int n_in,
                              void* d_out, int out_size)
{
    const float* feats = (const float*)d_in[0];
    const int*   tags  = (const int*)d_in[1];
    const float* trans = (const float*)d_in[2];
    float* out = (float*)d_out;
    crf_kernel<<<BB, 256>>>(feats, tags, trans, out);
}

// round 3
// speedup vs baseline: 1.3765x; 1.3765x over previous
#include <cuda_runtime.h>

#define BB 128
#define TT 4096
#define KK 64
#define START 62
#define STOP 63
#define NEGV -10000.0f

// backpointer scratch: 128 * 4096 * 64 = 32 MB
__device__ unsigned char g_bp[(size_t)BB * TT * KK];

__device__ __forceinline__ void barF() { asm volatile("bar.sync 1, 128;" ::: "memory"); }
__device__ __forceinline__ void barV() { asm volatile("bar.sync 2, 128;" ::: "memory"); }

__global__ __launch_bounds__(256, 1)
void crf_kernel(const float* __restrict__ feats,
                const int*   __restrict__ tags,
                const float* __restrict__ trans,
                float*       __restrict__ out)
{
    __shared__ __align__(16) float a_buf[2][KK];
    __shared__ __align__(16) float d_buf[2][KK];
    __shared__ float gred[128];
    __shared__ __align__(16) unsigned char bt[64 * KK];

    const int b   = blockIdx.x;
    const int tid = threadIdx.x;
    const float* bf = feats + (size_t)b * TT * KK;
    const int*   btags = tags + (size_t)b * TT;
    unsigned char* bpb = g_bp + (size_t)b * TT * KK;

    if (tid < 128) {
        // ---------------- FORWARD GROUP (warps 0-3), 2 threads per state ----------------
        const int j = tid >> 1;
        const int h = tid & 1;
        float E[32];
#pragma unroll
        for (int i = 0; i < 32; i++) E[i] = __expf(trans[j * KK + h * 32 + i]);

        if (h == 0) a_buf[0][j] = (j == START) ? 1.0f : 0.0f;

        float logscale = 0.0f;
        int p = 0;
        float f0 = bf[j];
        float f1 = bf[KK + j];
        barF();

        for (int t = 0; t < TT; t++) {
            float f2 = (t + 2 < TT) ? bf[(size_t)(t + 2) * KK + j] : 0.0f;

            const float4* av = (const float4*)(&a_buf[p][h * 32]);
            float d0 = 0.f, d1 = 0.f, d2 = 0.f, d3 = 0.f;
            float a0 = 0.f;
#pragma unroll
            for (int k = 0; k < 8; k++) {
                float4 a4 = av[k];
                if (k == 0) a0 = a4.x;           // h==0: this is a_prev[state 0]
                d0 = fmaf(E[4 * k + 0], a4.x, d0);
                d1 = fmaf(E[4 * k + 1], a4.y, d1);
                d2 = fmaf(E[4 * k + 2], a4.z, d2);
                d3 = fmaf(E[4 * k + 3], a4.w, d3);
            }
            float dot = (d0 + d1) + (d2 + d3);
            dot += __shfl_xor_sync(0xffffffffu, dot, 1);

            if (h == 0) {
                // renormalize by a_prev[0]; exact-in-expectation, barrier/reduction-free.
                float Ma = (t == 0) ? 1.0f : a0;  // first step: a_prev[0] == 0 (init vector)
                a_buf[p ^ 1][j] = __fdividef(__expf(f0) * dot, Ma);
                if (tid == 0) logscale += __logf(Ma);
            }
            barF();
            p ^= 1;
            f0 = f1; f1 = f2;
        }

        // ---- gold score (parallel over t) ----
        float g = 0.0f;
        for (int t = tid; t < TT; t += 128) {
            int tag  = btags[t];
            int prev = (t == 0) ? START : btags[t - 1];
            g += trans[tag * KK + prev] + bf[(size_t)t * KK + tag];
        }
        gred[tid] = g;
        barF();
        if (tid == 0) {
            float gold = 0.0f;
            for (int i = 0; i < 128; i++) gold += gred[i];
            gold += trans[STOP * KK + btags[TT - 1]];
            float s = 0.0f;
            for (int i = 0; i < KK; i++)
                s += a_buf[p][i] * __expf(trans[STOP * KK + i]);
            float fwd = logscale + __logf(s);
            out[b] = fwd - gold;   // nll
        }
    } else {
        // ---------------- VITERBI GROUP (warps 4-7), 2 threads per state ----------------
        const int vt = tid - 128;
        const int j = vt >> 1;
        const int h = vt & 1;
        float Tr[32];
#pragma unroll
        for (int i = 0; i < 32; i++) Tr[i] = trans[j * KK + h * 32 + i];

        if (h == 0) d_buf[0][j] = (j == START) ? 0.0f : NEGV;
        int p = 0;
        float f0 = bf[j];
        float f1 = bf[KK + j];
        barV();

        for (int t = 0; t < TT; t++) {
            float f2 = (t + 2 < TT) ? bf[(size_t)(t + 2) * KK + j] : 0.0f;

            const float4* dv = (const float4*)(&d_buf[p][h * 32]);
            float v[32];
#pragma unroll
            for (int k = 0; k < 8; k++) {
                float4 d4 = dv[k];
                v[4 * k + 0] = Tr[4 * k + 0] + d4.x;
                v[4 * k + 1] = Tr[4 * k + 1] + d4.y;
                v[4 * k + 2] = Tr[4 * k + 2] + d4.z;
                v[4 * k + 3] = Tr[4 * k + 3] + d4.w;
            }
            // value max: 4 parallel FMNMX chains, depth 8 (no predicates)
            float m0 = v[0], m1 = v[1], m2 = v[2], m3 = v[3];
#pragma unroll
            for (int k = 1; k < 8; k++) {
                m0 = fmaxf(m0, v[4 * k + 0]);
                m1 = fmaxf(m1, v[4 * k + 1]);
                m2 = fmaxf(m2, v[4 * k + 2]);
                m3 = fmaxf(m3, v[4 * k + 3]);
            }
            float Mh = fmaxf(fmaxf(m0, m1), fmaxf(m2, m3));
            float M  = fmaxf(Mh, __shfl_xor_sync(0xffffffffu, Mh, 1));

            // argmax: equality mask (fmax returns an input bitwise, so == is exact),
            // 4 parallel OR chains; smaller global index wins (first-max).
            unsigned ma0 = 0, ma1 = 0, ma2 = 0, ma3 = 0;
#pragma unroll
            for (int k = 0; k < 8; k++) {
                ma0 |= (v[4 * k + 0] == M) ? (1u << (4 * k + 0)) : 0u;
                ma1 |= (v[4 * k + 1] == M) ? (1u << (4 * k + 1)) : 0u;
                ma2 |= (v[4 * k + 2] == M) ? (1u << (4 * k + 2)) : 0u;
                ma3 |= (v[4 * k + 3] == M) ? (1u << (4 * k + 3)) : 0u;
            }
            unsigned mask = (ma0 | ma1) | (ma2 | ma3);
            int cand = mask ? (h * 32 + __ffs(mask) - 1) : 255;
            int oc = __shfl_xor_sync(0xffffffffu, cand, 1);
            cand = min(cand, oc);

            if (h == 0) {
                d_buf[p ^ 1][j] = M + f0;
                bpb[(size_t)t * KK + j] = (unsigned char)cand;
            }
            barV();
            p ^= 1;
            f0 = f1; f1 = f2;
        }

        // ---- terminal + path score (thread vt==0) ----
        int cur = 0;
        if (vt == 0) {
            float best = -3.0e38f; int blast = 0;
            for (int i = 0; i < KK; i++) {
                float vv = d_buf[p][i] + trans[STOP * KK + i];
                if (vv > best) { best = vv; blast = i; }
            }
            out[BB + b] = best;    // path_score
            cur = blast;
        }

        // ---- backtrack in 64-step chunks staged through shared ----
        float* pathout = out + 2 * BB + (size_t)b * TT;
        for (int t0 = TT - 64; t0 >= 0; t0 -= 64) {
            const uint4* src = (const uint4*)(bpb + (size_t)t0 * KK);
            uint4* dst = (uint4*)bt;
            dst[vt * 2 + 0] = src[vt * 2 + 0];
            dst[vt * 2 + 1] = src[vt * 2 + 1];
            barV();
            if (vt == 0) {
#pragma unroll 4
                for (int tt = 63; tt >= 0; tt--) {
                    pathout[t0 + tt] = (float)cur;
                    cur = bt[tt * KK + cur];
                }
            }
            barV();
        }
    }
}

extern "C" void kernel_launch(void* const* d_in, const int* in_sizes, int n_in,
                              void* d_out, int out_size)
{
    const float* feats = (const float*)d_in[0];
    const int*   tags  = (const int*)d_in[1];
    const float* trans = (const float*)d_in[2];
    float* out = (float*)d_out;
    crf_kernel<<<BB, 256>>>(feats, tags, trans, out);
}